// round 2
// baseline (speedup 1.0000x reference)
#include <cuda_runtime.h>

// NormmaxBisect: rows of d=2048, alpha=1.5 => p = clamp(x - tau, 0)^2,
// tau solves sum(clamp(x - tau,0)^3) = 1; output p / sum(p).
// One warp per row, row resident in registers as packed f32x2.
// 10 bisection passes (bracket to ~9.5e-4) + 3 Newton passes (fp32-exact tau)
// + 1 final pass (p = c^2, normalize). Matches 50-iter reference bisection to
// fp32 roundoff.

#define D 2048
#define WARPS_PER_BLOCK 8
#define THREADS (WARPS_PER_BLOCK * 32)
#define N_BISECT 10
#define N_NEWTON 3

typedef unsigned long long u64;

static __device__ __forceinline__ u64 pk2(float lo, float hi) {
    u64 r; asm("mov.b64 %0, {%1, %2};" : "=l"(r) : "f"(lo), "f"(hi)); return r;
}
static __device__ __forceinline__ void upk2(u64 v, float& lo, float& hi) {
    asm("mov.b64 {%0, %1}, %2;" : "=f"(lo), "=f"(hi) : "l"(v));
}
static __device__ __forceinline__ u64 add2(u64 a, u64 b) {
    u64 d; asm("add.rn.f32x2 %0, %1, %2;" : "=l"(d) : "l"(a), "l"(b)); return d;
}
static __device__ __forceinline__ u64 mul2(u64 a, u64 b) {
    u64 d; asm("mul.rn.f32x2 %0, %1, %2;" : "=l"(d) : "l"(a), "l"(b)); return d;
}
static __device__ __forceinline__ u64 fma2(u64 a, u64 b, u64 c) {
    u64 d; asm("fma.rn.f32x2 %0, %1, %2, %3;" : "=l"(d) : "l"(a), "l"(b), "l"(c)); return d;
}

// clamp both halves of a packed pair at 0 (FMNMX on the alu pipe)
static __device__ __forceinline__ u64 clamp2(u64 t) {
    float t0, t1; upk2(t, t0, t1);
    return pk2(fmaxf(t0, 0.0f), fmaxf(t1, 0.0f));
}

static __device__ __forceinline__ float warp_sum(float v) {
    #pragma unroll
    for (int o = 16; o; o >>= 1) v += __shfl_xor_sync(0xffffffffu, v, o);
    return v;
}

__global__ __launch_bounds__(THREADS)
void normmax_bisect_kernel(const float* __restrict__ X, float* __restrict__ O, int nrows) {
    const int warp = blockIdx.x * WARPS_PER_BLOCK + (threadIdx.x >> 5);
    if (warp >= nrows) return;
    const int lane = threadIdx.x & 31;

    const float4* __restrict__ src = reinterpret_cast<const float4*>(X + (size_t)warp * D);

    // Load row: 16 float4 per thread (coalesced: consecutive lanes -> consecutive float4)
    u64 xp[32];
    float mx = -3.4e38f;
    #pragma unroll
    for (int j = 0; j < 16; j++) {
        float4 v = src[j * 32 + lane];
        mx = fmaxf(mx, fmaxf(fmaxf(v.x, v.y), fmaxf(v.z, v.w)));
        xp[2 * j]     = pk2(v.x, v.y);
        xp[2 * j + 1] = pk2(v.z, v.w);
    }
    #pragma unroll
    for (int o = 16; o; o >>= 1) mx = fmaxf(mx, __shfl_xor_sync(0xffffffffu, mx, o));

    // Bracket: tau_lo = max - 1, dm0 = tau_hi - tau_lo = 1 - (1/2048)^0.5
    float tau_lo = mx - 1.0f;
    float dm = 0.9779029130879204f;

    // ---- 10 bisection passes: only need s3 = sum(c^3) ----
    for (int it = 0; it < N_BISECT; ++it) {
        dm *= 0.5f;
        const float tau_m = tau_lo + dm;
        const u64 nt = pk2(-tau_m, -tau_m);
        u64 sa = 0ull, sb = 0ull;
        #pragma unroll
        for (int i = 0; i < 32; i += 2) {
            {
                u64 c  = clamp2(add2(xp[i], nt));
                u64 c2 = mul2(c, c);
                sa = fma2(c2, c, sa);
            }
            {
                u64 c  = clamp2(add2(xp[i + 1], nt));
                u64 c2 = mul2(c, c);
                sb = fma2(c2, c, sb);
            }
        }
        float l, h; upk2(add2(sa, sb), l, h);
        const float s3 = warp_sum(l + h);
        if (s3 >= 1.0f) tau_lo = tau_m;   // uniform across warp
    }

    // ---- 3 Newton passes from the f>=0 side (convex => monotone, no overshoot) ----
    float tau = tau_lo;
    for (int it = 0; it < N_NEWTON; ++it) {
        const u64 nt = pk2(-tau, -tau);
        u64 s2a = 0ull, s2b = 0ull, s3a = 0ull, s3b = 0ull;
        #pragma unroll
        for (int i = 0; i < 32; i += 2) {
            {
                u64 c  = clamp2(add2(xp[i], nt));
                u64 c2 = mul2(c, c);
                s2a = add2(s2a, c2);
                s3a = fma2(c2, c, s3a);
            }
            {
                u64 c  = clamp2(add2(xp[i + 1], nt));
                u64 c2 = mul2(c, c);
                s2b = add2(s2b, c2);
                s3b = fma2(c2, c, s3b);
            }
        }
        float l, h;
        upk2(add2(s2a, s2b), l, h);
        const float s2 = warp_sum(l + h);
        upk2(add2(s3a, s3b), l, h);
        const float s3 = warp_sum(l + h);
        // f = s3 - 1, f' = -3*s2 ; at the root s2 >= (sum c^3)^(2/3) ~= 1, no div hazard
        tau += __fdividef(s3 - 1.0f, 3.0f * s2);
    }

    // ---- Final pass: p = c^2 (stored in xp), normalize by sum(p) ----
    {
        const u64 nt = pk2(-tau, -tau);
        u64 s2a = 0ull, s2b = 0ull;
        #pragma unroll
        for (int i = 0; i < 32; i += 2) {
            {
                u64 c  = clamp2(add2(xp[i], nt));
                u64 c2 = mul2(c, c);
                xp[i] = c2;
                s2a = add2(s2a, c2);
            }
            {
                u64 c  = clamp2(add2(xp[i + 1], nt));
                u64 c2 = mul2(c, c);
                xp[i + 1] = c2;
                s2b = add2(s2b, c2);
            }
        }
        float l, h; upk2(add2(s2a, s2b), l, h);
        const float s2 = warp_sum(l + h);
        const float inv = __fdividef(1.0f, s2);
        const u64 iv = pk2(inv, inv);

        float4* __restrict__ dst = reinterpret_cast<float4*>(O + (size_t)warp * D);
        #pragma unroll
        for (int j = 0; j < 16; j++) {
            u64 p0 = mul2(xp[2 * j], iv);
            u64 p1 = mul2(xp[2 * j + 1], iv);
            float a, b, c, d;
            upk2(p0, a, b);
            upk2(p1, c, d);
            dst[j * 32 + lane] = make_float4(a, b, c, d);
        }
    }
}

extern "C" void kernel_launch(void* const* d_in, const int* in_sizes, int n_in,
                              void* d_out, int out_size) {
    const float* X = (const float*)d_in[0];
    float* O = (float*)d_out;
    const int nrows = in_sizes[0] / D;               // 65536
    const int grid = (nrows + WARPS_PER_BLOCK - 1) / WARPS_PER_BLOCK;
    normmax_bisect_kernel<<<grid, THREADS>>>(X, O, nrows);
}

// round 3
// speedup vs baseline: 1.0999x; 1.0999x over previous
#include <cuda_runtime.h>

// NormmaxBisect, alpha=1.5, d=2048: p = clamp(x - tau, 0)^2 / sum(...),
// tau solves sum(clamp(x - tau, 0)^3) = 1.
//
// Active-set kernel: tau >= max-1 always, so only elements x > max-1 ever
// contribute to the solver sums. One warp per row:
//   1) load row into registers, warp-max
//   2) compact actives (x > max-1) into a per-warp smem buffer (2-scan + prefix)
//   3) 12 bisection + 3 Newton passes over the tiny active set (fp32-exact tau)
//   4) one full-row pass: p = clamp(x-tau)^2 * (1/sum), streamed out
// Fallback (cnt > CAP, statistically impossible here): solve over full register row.

#define D 2048
#define WPB 8
#define THREADS (WPB * 32)
#define CAP 1024                 // per-warp active buffer; 8*1024*4 = 32KB static smem
#define N_BISECT 12
#define N_NEWTON 3
#define DM0 0.9779029130879204f  // 1 - (1/2048)^0.5

static __device__ __forceinline__ float warp_sum(float v) {
    #pragma unroll
    for (int o = 16; o; o >>= 1) v += __shfl_xor_sync(0xffffffffu, v, o);
    return v;
}
static __device__ __forceinline__ float warp_max(float v) {
    #pragma unroll
    for (int o = 16; o; o >>= 1) v = fmaxf(v, __shfl_xor_sync(0xffffffffu, v, o));
    return v;
}

// --- sums over compacted smem actives ---
static __device__ __forceinline__ float s3_smem(const float* sbuf, int nv, int lane, float tau) {
    float s3 = 0.0f;
    for (int i = 0; i < nv; ++i) {
        float c = fmaxf(sbuf[i * 32 + lane] - tau, 0.0f);
        s3 = fmaf(c * c, c, s3);
    }
    return warp_sum(s3);
}
static __device__ __forceinline__ void s23_smem(const float* sbuf, int nv, int lane, float tau,
                                                float& s2o, float& s3o) {
    float s2 = 0.0f, s3 = 0.0f;
    for (int i = 0; i < nv; ++i) {
        float c = fmaxf(sbuf[i * 32 + lane] - tau, 0.0f);
        float c2 = c * c;
        s2 += c2;
        s3 = fmaf(c2, c, s3);
    }
    s2o = warp_sum(s2);
    s3o = warp_sum(s3);
}

// --- sums over the full register-resident row (fallback path) ---
static __device__ __forceinline__ float s3_regs(const float4* v, float tau) {
    float s3 = 0.0f;
    #pragma unroll
    for (int j = 0; j < 16; ++j) {
        float cx = fmaxf(v[j].x - tau, 0.0f);
        float cy = fmaxf(v[j].y - tau, 0.0f);
        float cz = fmaxf(v[j].z - tau, 0.0f);
        float cw = fmaxf(v[j].w - tau, 0.0f);
        s3 = fmaf(cx * cx, cx, s3);
        s3 = fmaf(cy * cy, cy, s3);
        s3 = fmaf(cz * cz, cz, s3);
        s3 = fmaf(cw * cw, cw, s3);
    }
    return warp_sum(s3);
}
static __device__ __forceinline__ void s23_regs(const float4* v, float tau, float& s2o, float& s3o) {
    float s2 = 0.0f, s3 = 0.0f;
    #pragma unroll
    for (int j = 0; j < 16; ++j) {
        float cx = fmaxf(v[j].x - tau, 0.0f);
        float cy = fmaxf(v[j].y - tau, 0.0f);
        float cz = fmaxf(v[j].z - tau, 0.0f);
        float cw = fmaxf(v[j].w - tau, 0.0f);
        float c2x = cx * cx, c2y = cy * cy, c2z = cz * cz, c2w = cw * cw;
        s2 += c2x + c2y + c2z + c2w;
        s3 = fmaf(c2x, cx, s3);
        s3 = fmaf(c2y, cy, s3);
        s3 = fmaf(c2z, cz, s3);
        s3 = fmaf(c2w, cw, s3);
    }
    s2o = warp_sum(s2);
    s3o = warp_sum(s3);
}

__global__ __launch_bounds__(THREADS, 2)
void normmax_active_kernel(const float* __restrict__ X, float* __restrict__ O, int nrows) {
    __shared__ float sbuf_all[WPB * CAP];
    const int warp = blockIdx.x * WPB + (threadIdx.x >> 5);
    if (warp >= nrows) return;
    const int lane = threadIdx.x & 31;
    float* sbuf = sbuf_all + (threadIdx.x >> 5) * CAP;

    const float4* __restrict__ src = reinterpret_cast<const float4*>(X + (size_t)warp * D);

    // ---- load row (coalesced) + warp max ----
    float4 v[16];
    float mx = -3.4e38f;
    #pragma unroll
    for (int j = 0; j < 16; ++j) {
        float4 t = src[j * 32 + lane];
        v[j] = t;
        mx = fmaxf(mx, fmaxf(fmaxf(t.x, t.y), fmaxf(t.z, t.w)));
    }
    mx = warp_max(mx);
    const float thr = mx - 1.0f;   // = tau_lo; only x > thr can ever contribute

    // ---- scan 1: count actives per lane ----
    int cnt = 0;
    #pragma unroll
    for (int j = 0; j < 16; ++j) {
        cnt += (v[j].x > thr) + (v[j].y > thr) + (v[j].z > thr) + (v[j].w > thr);
    }
    // inclusive warp prefix sum
    int pre = cnt;
    #pragma unroll
    for (int o = 1; o < 32; o <<= 1) {
        int t = __shfl_up_sync(0xffffffffu, pre, o);
        if (lane >= o) pre += t;
    }
    const int total = __shfl_sync(0xffffffffu, pre, 31);

    float tau;
    int nv = 0;
    if (total <= CAP) {
        // ---- scan 2: compact actives into smem ----
        int k = pre - cnt;  // exclusive base
        #pragma unroll
        for (int j = 0; j < 16; ++j) {
            if (v[j].x > thr) sbuf[k++] = v[j].x;
            if (v[j].y > thr) sbuf[k++] = v[j].y;
            if (v[j].z > thr) sbuf[k++] = v[j].z;
            if (v[j].w > thr) sbuf[k++] = v[j].w;
        }
        nv = (total + 31) >> 5;
        // pad last chunk so every lane reads a harmless value
        for (int i = total + lane; i < nv * 32; i += 32) sbuf[i] = -1e30f;
        __syncwarp();

        // ---- bisection on actives ----
        float tau_lo = thr;
        float dm = DM0;
        #pragma unroll
        for (int it = 0; it < N_BISECT; ++it) {
            dm *= 0.5f;
            const float tm = tau_lo + dm;
            if (s3_smem(sbuf, nv, lane, tm) >= 1.0f) tau_lo = tm;  // warp-uniform
        }
        // ---- Newton (convex f, from f>=0 side: monotone, no overshoot) ----
        tau = tau_lo;
        #pragma unroll
        for (int it = 0; it < N_NEWTON; ++it) {
            float s2, s3;
            s23_smem(sbuf, nv, lane, tau, s2, s3);
            tau += __fdividef(s3 - 1.0f, 3.0f * s2);
        }
    } else {
        // ---- fallback: solve over the full register row (never taken for this input) ----
        float tau_lo = thr;
        float dm = DM0;
        for (int it = 0; it < N_BISECT + 8; ++it) {   // extra bisections for safety
            dm *= 0.5f;
            const float tm = tau_lo + dm;
            if (s3_regs(v, tm) >= 1.0f) tau_lo = tm;
        }
        tau = tau_lo;
        for (int it = 0; it < N_NEWTON; ++it) {
            float s2, s3;
            s23_regs(v, tau, s2, s3);
            tau += __fdividef(s3 - 1.0f, 3.0f * s2);
        }
    }

    // ---- normalization constant: sum(c^2) at final tau ----
    float s2;
    if (total <= CAP) {
        float acc = 0.0f;
        for (int i = 0; i < nv; ++i) {
            float c = fmaxf(sbuf[i * 32 + lane] - tau, 0.0f);
            acc = fmaf(c, c, acc);
        }
        s2 = warp_sum(acc);
    } else {
        float dummy;
        s23_regs(v, tau, s2, dummy);
    }
    const float inv = __fdividef(1.0f, s2);

    // ---- final pass: p = clamp(x - tau)^2 * inv, streamed out ----
    float4* __restrict__ dst = reinterpret_cast<float4*>(O + (size_t)warp * D);
    #pragma unroll
    for (int j = 0; j < 16; ++j) {
        float cx = fmaxf(v[j].x - tau, 0.0f);
        float cy = fmaxf(v[j].y - tau, 0.0f);
        float cz = fmaxf(v[j].z - tau, 0.0f);
        float cw = fmaxf(v[j].w - tau, 0.0f);
        float4 p;
        p.x = cx * cx * inv;
        p.y = cy * cy * inv;
        p.z = cz * cz * inv;
        p.w = cw * cw * inv;
        dst[j * 32 + lane] = p;
    }
}

extern "C" void kernel_launch(void* const* d_in, const int* in_sizes, int n_in,
                              void* d_out, int out_size) {
    const float* X = (const float*)d_in[0];
    float* O = (float*)d_out;
    const int nrows = in_sizes[0] / D;                 // 65536
    const int grid = (nrows + WPB - 1) / WPB;
    normmax_active_kernel<<<grid, THREADS>>>(X, O, nrows);
}